// round 10
// baseline (speedup 1.0000x reference)
#include <cuda_runtime.h>
#include <cuda_fp16.h>
#include <cuda_bf16.h>
#include <cuda_pipeline_primitives.h>

// Problem shapes (fixed by the dataset):
//   text:        [16, 2048, 256] f32      d_in[0]
//   const_mat:   [16, 2048, 2048] i32     d_in[1]   (UNUSED: softmax rows sum to 1)
//   const_labels:[16, 2048, 8] i32        d_in[2]
//   emb_table:   [100, 128] f32           d_in[3]
//   attn_W:      [256, 384] f32           d_in[4]   (UNUSED: cancels in softmax)
//   attn_b:      [256] f32                d_in[5]   (UNUSED)
//   fc_W:        [256, 128] f32           d_in[6]
//   fc_b:        [256] f32                d_in[7]
//   out:         [16, 2048, 256] f32
//
// Collapse: out[pos,d] = relu( text[pos,d] + sum_{k=0..7} G[labels[pos,k], d] )
// with G[n,d] = 0.125 * (fc_b[d] + emb_table[n] . fc_W[d]), G stored fp16.
//
// R10: cp.async text pipeline. R6-R9 all landed at 14.0-14.6us because every
// variant shared the same invariant: text misses L2 each replay (~35 MB DRAM
// traffic measured) and per-thread scoreboards can't hold enough outstanding
// 600-cyc misses. LDGSTS tracks completion via commit groups, so each CTA
// queues its ENTIRE 32 KB text span at launch and consumes tile-by-tile.

#define CN    100
#define CD    128
#define DIM   256
#define KLBL  8

#define FG_CTAS     1024
#define POS_PER_CTA 32          // 1024 * 32 = 32768 positions
#define TILE_POS    8
#define NTILES      4           // POS_PER_CTA / TILE_POS
#define FG_THREADS  256

__device__ __half g_Gh[CN * DIM];  // 50 KB fp16 table

// ---------------------------------------------------------------------------
// Kernel A: G[n,d] = 0.125 * (fc_b[d] + sum_c emb_table[n,c] * fc_W[d,c]) -> fp16
// ---------------------------------------------------------------------------
__global__ void __launch_bounds__(DIM) build_G_kernel(
    const float* __restrict__ emb_table,
    const float* __restrict__ fc_W,
    const float* __restrict__ fc_b)
{
    __shared__ float se[CD];
    const int n = blockIdx.x;
    const int d = threadIdx.x;
    if (d < CD) se[d] = emb_table[n * CD + d];
    __syncthreads();

    const float4* w4 = reinterpret_cast<const float4*>(fc_W + d * CD);
    float acc = fc_b[d];
    #pragma unroll
    for (int c4 = 0; c4 < CD / 4; c4++) {
        float4 w = __ldg(w4 + c4);
        acc = fmaf(se[c4 * 4 + 0], w.x, acc);
        acc = fmaf(se[c4 * 4 + 1], w.y, acc);
        acc = fmaf(se[c4 * 4 + 2], w.z, acc);
        acc = fmaf(se[c4 * 4 + 3], w.w, acc);
    }
    g_Gh[n * DIM + d] = __float2half_rn(0.125f * acc);
}

// ---------------------------------------------------------------------------
// Kernel B: fused gather-add-relu with cp.async text/label prefetch.
// CTA = 256 thr, 32 contiguous positions. Warp w handles position t*8+w of
// tile t. Per warp-pos: 16 LDG.64 G-gathers + 2 LDS.128 text + 2 STG.128 out.
// ---------------------------------------------------------------------------
__device__ __forceinline__ __half2 as_h2(unsigned u) {
    return *reinterpret_cast<const __half2*>(&u);
}

__device__ __forceinline__ float4 reduce8(
    const uint2& u0, const uint2& u1, const uint2& u2, const uint2& u3,
    const uint2& u4, const uint2& u5, const uint2& u6, const uint2& u7,
    const float4& t)
{
    const __half2 p0lo = __hadd2(as_h2(u0.x), as_h2(u1.x));
    const __half2 p0hi = __hadd2(as_h2(u0.y), as_h2(u1.y));
    const __half2 p1lo = __hadd2(as_h2(u2.x), as_h2(u3.x));
    const __half2 p1hi = __hadd2(as_h2(u2.y), as_h2(u3.y));
    const __half2 p2lo = __hadd2(as_h2(u4.x), as_h2(u5.x));
    const __half2 p2hi = __hadd2(as_h2(u4.y), as_h2(u5.y));
    const __half2 p3lo = __hadd2(as_h2(u6.x), as_h2(u7.x));
    const __half2 p3hi = __hadd2(as_h2(u6.y), as_h2(u7.y));

    const float2 f0lo = __half22float2(p0lo);
    const float2 f1lo = __half22float2(p1lo);
    const float2 f2lo = __half22float2(p2lo);
    const float2 f3lo = __half22float2(p3lo);
    const float2 f0hi = __half22float2(p0hi);
    const float2 f1hi = __half22float2(p1hi);
    const float2 f2hi = __half22float2(p2hi);
    const float2 f3hi = __half22float2(p3hi);

    float4 r;
    r.x = fmaxf(t.x + (f0lo.x + f1lo.x) + (f2lo.x + f3lo.x), 0.0f);
    r.y = fmaxf(t.y + (f0lo.y + f1lo.y) + (f2lo.y + f3lo.y), 0.0f);
    r.z = fmaxf(t.z + (f0hi.x + f1hi.x) + (f2hi.x + f3hi.x), 0.0f);
    r.w = fmaxf(t.w + (f0hi.y + f1hi.y) + (f2hi.y + f3hi.y), 0.0f);
    return r;
}

__global__ void __launch_bounds__(FG_THREADS) fused_gather_kernel(
    const float4* __restrict__ text4,   // [npos*64]
    const int4*   __restrict__ labels4, // [npos*2]
    float4*       __restrict__ out4)    // [npos*64]
{
    __shared__ float4 sText[POS_PER_CTA * 64];  // 32 KB
    __shared__ int4   sLab[POS_PER_CTA * 2];    // 1 KB

    const int base = blockIdx.x * POS_PER_CTA;  // first position of this CTA

    // ---- Prefetch: labels + tile 0 as group 0, tiles 1..3 as groups 1..3.
    if (threadIdx.x < POS_PER_CTA * 2) {
        __pipeline_memcpy_async(&sLab[threadIdx.x],
                                &labels4[base * 2 + threadIdx.x], 16);
    }
    #pragma unroll
    for (int t = 0; t < NTILES; t++) {
        #pragma unroll
        for (int i = threadIdx.x; i < TILE_POS * 64; i += FG_THREADS) {
            __pipeline_memcpy_async(&sText[t * (TILE_POS * 64) + i],
                                    &text4[base * 64 + t * (TILE_POS * 64) + i], 16);
        }
        __pipeline_commit();
    }

    const int wid  = threadIdx.x >> 5;
    const int lane = threadIdx.x & 31;

    const uint2* __restrict__ Gh = reinterpret_cast<const uint2*>(g_Gh);

    #pragma unroll
    for (int t = 0; t < NTILES; t++) {
        __pipeline_wait_prior(NTILES - 1 - t);
        __syncthreads();   // tile t (and labels at t=0) visible to all warps

        const int p = t * TILE_POS + wid;      // local position 0..31
        const int4 l0 = sLab[p * 2 + 0];       // LDS broadcast
        const int4 l1 = sLab[p * 2 + 1];

        const int b0 = (l0.x << 6) + lane;
        const int b1 = (l0.y << 6) + lane;
        const int b2 = (l0.z << 6) + lane;
        const int b3 = (l0.w << 6) + lane;
        const int b4 = (l1.x << 6) + lane;
        const int b5 = (l1.y << 6) + lane;
        const int b6 = (l1.z << 6) + lane;
        const int b7 = (l1.w << 6) + lane;

        const uint2 a0 = __ldg(Gh + b0);
        const uint2 a1 = __ldg(Gh + b1);
        const uint2 a2 = __ldg(Gh + b2);
        const uint2 a3 = __ldg(Gh + b3);
        const uint2 a4 = __ldg(Gh + b4);
        const uint2 a5 = __ldg(Gh + b5);
        const uint2 a6 = __ldg(Gh + b6);
        const uint2 a7 = __ldg(Gh + b7);

        const uint2 c0 = __ldg(Gh + b0 + 32);
        const uint2 c1 = __ldg(Gh + b1 + 32);
        const uint2 c2 = __ldg(Gh + b2 + 32);
        const uint2 c3 = __ldg(Gh + b3 + 32);
        const uint2 c4 = __ldg(Gh + b4 + 32);
        const uint2 c5 = __ldg(Gh + b5 + 32);
        const uint2 c6 = __ldg(Gh + b6 + 32);
        const uint2 c7 = __ldg(Gh + b7 + 32);

        const float4 tA = sText[p * 64 + lane];
        const float4 tB = sText[p * 64 + lane + 32];

        const float4 rA = reduce8(a0, a1, a2, a3, a4, a5, a6, a7, tA);
        const float4 rB = reduce8(c0, c1, c2, c3, c4, c5, c6, c7, tB);

        const int go = (base + p) * 64 + lane;
        __stcs(out4 + go, rA);
        __stcs(out4 + go + 32, rB);
    }
}

// ---------------------------------------------------------------------------
extern "C" void kernel_launch(void* const* d_in, const int* in_sizes, int n_in,
                              void* d_out, int out_size)
{
    const float* text      = (const float*)d_in[0];
    const int*   labels    = (const int*)  d_in[2];
    const float* emb_table = (const float*)d_in[3];
    const float* fc_W      = (const float*)d_in[6];
    const float* fc_b      = (const float*)d_in[7];
    float*       out       = (float*)d_out;

    build_G_kernel<<<CN, DIM>>>(emb_table, fc_W, fc_b);

    fused_gather_kernel<<<FG_CTAS, FG_THREADS>>>(
        reinterpret_cast<const float4*>(text),
        reinterpret_cast<const int4*>(labels),
        reinterpret_cast<float4*>(out));
}

// round 12
// speedup vs baseline: 1.1458x; 1.1458x over previous
#include <cuda_runtime.h>
#include <cuda_fp16.h>
#include <cuda_bf16.h>

// Problem shapes (fixed by the dataset):
//   text:        [16, 2048, 256] f32      d_in[0]
//   const_mat:   [16, 2048, 2048] i32     d_in[1]   (UNUSED: softmax rows sum to 1)
//   const_labels:[16, 2048, 8] i32        d_in[2]
//   emb_table:   [100, 128] f32           d_in[3]
//   attn_W:      [256, 384] f32           d_in[4]   (UNUSED: cancels in softmax)
//   attn_b:      [256] f32                d_in[5]   (UNUSED)
//   fc_W:        [256, 128] f32           d_in[6]
//   fc_b:        [256] f32                d_in[7]
//   out:         [16, 2048, 256] f32
//
// Collapse: out[pos,d] = relu( text[pos,d] + sum_{k=0..7} G[labels[pos,k], d] )
// with G[n,d] = 0.125 * (fc_b[d] + emb_table[n] . fc_W[d]), G stored fp16.
//
// R12 = R7 body + ld.global.lu on text. text is read exactly once per replay:
// last-use hint evicts it from L1 immediately (keeping the 50 KB G table
// L1-resident) while leaving L2 policy alone (text must stay L2-resident
// across graph replays -- the R6 .cs experiment showed L2 eviction costs
// ~35 MB/replay of DRAM refetch). tcgen05 path is dead: harness ptxas target
// is compute_103, which rejects all tcgen05/TMEM instructions.

#define CN    100
#define CD    128
#define DIM   256
#define KLBL  8

__device__ __half g_Gh[CN * DIM];  // 50 KB fp16 table

// ---------------------------------------------------------------------------
// Kernel A: G[n,d] = 0.125 * (fc_b[d] + sum_c emb_table[n,c] * fc_W[d,c]) -> fp16
// ---------------------------------------------------------------------------
__global__ void __launch_bounds__(DIM) build_G_kernel(
    const float* __restrict__ emb_table,
    const float* __restrict__ fc_W,
    const float* __restrict__ fc_b)
{
    __shared__ float se[CD];
    const int n = blockIdx.x;
    const int d = threadIdx.x;
    if (d < CD) se[d] = emb_table[n * CD + d];
    __syncthreads();

    const float4* w4 = reinterpret_cast<const float4*>(fc_W + d * CD);
    float acc = fc_b[d];
    #pragma unroll
    for (int c4 = 0; c4 < CD / 4; c4++) {
        float4 w = __ldg(w4 + c4);
        acc = fmaf(se[c4 * 4 + 0], w.x, acc);
        acc = fmaf(se[c4 * 4 + 1], w.y, acc);
        acc = fmaf(se[c4 * 4 + 2], w.z, acc);
        acc = fmaf(se[c4 * 4 + 3], w.w, acc);
    }
    g_Gh[n * DIM + d] = __float2half_rn(0.125f * acc);
}

// ---------------------------------------------------------------------------
// Kernel B: fused gather-add-relu. gid -> pos = gid>>5, d4 = gid&31.
// Thread covers output float4s (pos, d4) and (pos, d4+32).
// ---------------------------------------------------------------------------
__device__ __forceinline__ __half2 as_h2(unsigned u) {
    return *reinterpret_cast<const __half2*>(&u);
}

// ld.global.lu float4: last-use in L1 (evict-first locally), default L2.
__device__ __forceinline__ float4 ldlu_f4(const float4* p) {
    float4 v;
    asm volatile("ld.global.lu.v4.f32 {%0,%1,%2,%3}, [%4];"
                 : "=f"(v.x), "=f"(v.y), "=f"(v.z), "=f"(v.w)
                 : "l"(p));
    return v;
}

__device__ __forceinline__ float4 reduce8(
    const uint2& u0, const uint2& u1, const uint2& u2, const uint2& u3,
    const uint2& u4, const uint2& u5, const uint2& u6, const uint2& u7,
    const float4& t)
{
    // One HADD2 level in fp16, then fp32 finish.
    const __half2 p0lo = __hadd2(as_h2(u0.x), as_h2(u1.x));
    const __half2 p0hi = __hadd2(as_h2(u0.y), as_h2(u1.y));
    const __half2 p1lo = __hadd2(as_h2(u2.x), as_h2(u3.x));
    const __half2 p1hi = __hadd2(as_h2(u2.y), as_h2(u3.y));
    const __half2 p2lo = __hadd2(as_h2(u4.x), as_h2(u5.x));
    const __half2 p2hi = __hadd2(as_h2(u4.y), as_h2(u5.y));
    const __half2 p3lo = __hadd2(as_h2(u6.x), as_h2(u7.x));
    const __half2 p3hi = __hadd2(as_h2(u6.y), as_h2(u7.y));

    const float2 f0lo = __half22float2(p0lo);
    const float2 f1lo = __half22float2(p1lo);
    const float2 f2lo = __half22float2(p2lo);
    const float2 f3lo = __half22float2(p3lo);
    const float2 f0hi = __half22float2(p0hi);
    const float2 f1hi = __half22float2(p1hi);
    const float2 f2hi = __half22float2(p2hi);
    const float2 f3hi = __half22float2(p3hi);

    float4 r;
    r.x = fmaxf(t.x + (f0lo.x + f1lo.x) + (f2lo.x + f3lo.x), 0.0f);
    r.y = fmaxf(t.y + (f0lo.y + f1lo.y) + (f2lo.y + f3lo.y), 0.0f);
    r.z = fmaxf(t.z + (f0hi.x + f1hi.x) + (f2hi.x + f3hi.x), 0.0f);
    r.w = fmaxf(t.w + (f0hi.y + f1hi.y) + (f2hi.y + f3hi.y), 0.0f);
    return r;
}

__global__ void __launch_bounds__(256, 6) fused_gather_kernel(
    const float4* __restrict__ text4,
    const int*    __restrict__ labels,
    float4*       __restrict__ out4)
{
    const int gid = blockIdx.x * blockDim.x + threadIdx.x;   // exact grid

    const int pos = gid >> 5;        // warp-uniform (warp = one position)
    const int d4  = gid & 31;        // uint2 slot 0..31; twin at d4+32

    const int4* lb = reinterpret_cast<const int4*>(labels) + (pos << 1);
    const int4 l0 = __ldg(lb + 0);
    const int4 l1 = __ldg(lb + 1);

    const uint2* __restrict__ Gh = reinterpret_cast<const uint2*>(g_Gh);

    const int idxA = (pos << 6) + d4;        // output float4 index, low half
    const int idxB = idxA + 32;              // high half

    // Text: last-use in L1, default L2 (stays resident across replays).
    const float4 tA = ldlu_f4(text4 + idxA);
    const float4 tB = ldlu_f4(text4 + idxB);

    const int b0 = (l0.x << 6) + d4;
    const int b1 = (l0.y << 6) + d4;
    const int b2 = (l0.z << 6) + d4;
    const int b3 = (l0.w << 6) + d4;
    const int b4 = (l1.x << 6) + d4;
    const int b5 = (l1.y << 6) + d4;
    const int b6 = (l1.z << 6) + d4;
    const int b7 = (l1.w << 6) + d4;

    const uint2 a0 = __ldg(Gh + b0);
    const uint2 a1 = __ldg(Gh + b1);
    const uint2 a2 = __ldg(Gh + b2);
    const uint2 a3 = __ldg(Gh + b3);
    const uint2 a4 = __ldg(Gh + b4);
    const uint2 a5 = __ldg(Gh + b5);
    const uint2 a6 = __ldg(Gh + b6);
    const uint2 a7 = __ldg(Gh + b7);

    const uint2 c0 = __ldg(Gh + b0 + 32);
    const uint2 c1 = __ldg(Gh + b1 + 32);
    const uint2 c2 = __ldg(Gh + b2 + 32);
    const uint2 c3 = __ldg(Gh + b3 + 32);
    const uint2 c4 = __ldg(Gh + b4 + 32);
    const uint2 c5 = __ldg(Gh + b5 + 32);
    const uint2 c6 = __ldg(Gh + b6 + 32);
    const uint2 c7 = __ldg(Gh + b7 + 32);

    const float4 rA = reduce8(a0, a1, a2, a3, a4, a5, a6, a7, tA);
    const float4 rB = reduce8(c0, c1, c2, c3, c4, c5, c6, c7, tB);

    // Stores: evict-first everywhere (written once, never re-read here).
    __stcs(out4 + idxA, rA);
    __stcs(out4 + idxB, rB);
}

// ---------------------------------------------------------------------------
extern "C" void kernel_launch(void* const* d_in, const int* in_sizes, int n_in,
                              void* d_out, int out_size)
{
    const float* text      = (const float*)d_in[0];
    const int*   labels    = (const int*)  d_in[2];
    const float* emb_table = (const float*)d_in[3];
    const float* fc_W      = (const float*)d_in[6];
    const float* fc_b      = (const float*)d_in[7];
    float*       out       = (float*)d_out;

    const int ntotal = in_sizes[0];        // 8,388,608
    const int nhalf  = ntotal / 8;         // 1,048,576 threads (2 float4 each)

    build_G_kernel<<<CN, DIM>>>(emb_table, fc_W, fc_b);

    const int block = 256;
    const int grid  = nhalf / block;       // 4096 exactly
    fused_gather_kernel<<<grid, block>>>(
        reinterpret_cast<const float4*>(text),
        labels,
        reinterpret_cast<float4*>(out));
}